// round 9
// baseline (speedup 1.0000x reference)
#include <cuda_runtime.h>
#include <math.h>

#define BB 2
#define HH 720
#define WW 1280
#define HW (HH*WW)
#define NPIX (BB*HW)
#define EPSF 1e-7f

// Scratch: splat accumulators [dir][b][pixel][4ch]  (~59 MB)
__device__ __align__(16) float g_acc[(size_t)2 * BB * HW * 4];

// ---------------------------------------------------------------------------
// Splat kernel, ONE (direction, batch) per launch. 1 px/thread; REDG floor.
// Pointers pre-offset to the batch. float4 atomicAdd -> RED.E.128 per corner.
// ---------------------------------------------------------------------------
__global__ void __launch_bounds__(256) splat_db_kernel(
    const float* __restrict__ img, const float* __restrict__ fl,
    const float* __restrict__ zz, float4* __restrict__ acc)
{
    int p = blockIdx.x * blockDim.x + threadIdx.x;
    if (p >= HW) return;
    int y = p / WW;
    int x = p - y * WW;

    float fx = (float)x + 0.5f * fl[(size_t)1 * HW + p];
    float fy = (float)y + 0.5f * fl[p];
    float w  = __expf(zz[p]);
    float vr = img[p] * w;
    float vg = img[(size_t)1 * HW + p] * w;
    float vb = img[(size_t)2 * HW + p] * w;

    float x0f = floorf(fx), y0f = floorf(fy);
    int ix0 = (int)x0f, iy0 = (int)y0f;
    float ax = fx - x0f, ay = fy - y0f;

#pragma unroll
    for (int cy = 0; cy < 2; ++cy) {
        int ty = iy0 + cy;
        if ((unsigned)ty >= (unsigned)HH) continue;
        float wy = cy ? ay : (1.0f - ay);
#pragma unroll
        for (int cx = 0; cx < 2; ++cx) {
            int tx = ix0 + cx;
            if ((unsigned)tx >= (unsigned)WW) continue;
            float wt = wy * (cx ? ax : (1.0f - ax));
            atomicAdd(acc + ((size_t)ty * WW + tx),
                      make_float4(vr * wt, vg * wt, vb * wt, w * wt));
        }
    }
}

// ---------------------------------------------------------------------------
// Flow channels (12-15): out = 0.5 * flow. Pure DRAM copy; runs concurrent
// with the atomic-bound splat phase. float4 vectorized, streaming hints.
// ---------------------------------------------------------------------------
#define FQ (BB * 2 * HW / 4)
__global__ void __launch_bounds__(256) flow_copy_kernel(
    const float4* __restrict__ f0, const float4* __restrict__ f1,
    float4* __restrict__ out)
{
    int i = blockIdx.x * blockDim.x + threadIdx.x;
    if (i >= FQ) return;
    const int CH4 = HW / 4;
    int b = i / (2 * CH4);
    int rem = i - b * (2 * CH4);
    int c = rem / CH4;
    int p4 = rem - c * CH4;

    float4 q0 = __ldcs(f0 + i);
    float4 q1 = __ldcs(f1 + i);
    float4 h0 = make_float4(0.5f*q0.x, 0.5f*q0.y, 0.5f*q0.z, 0.5f*q0.w);
    float4 h1 = make_float4(0.5f*q1.x, 0.5f*q1.y, 0.5f*q1.z, 0.5f*q1.w);
    __stcs(out + (size_t)(b * 18 + 12 + c) * CH4 + p4, h0);
    __stcs(out + (size_t)(b * 18 + 14 + c) * CH4 + p4, h1);
}

// ---------------------------------------------------------------------------
// Fused normalize + morphological open + compose (flows removed).
// Tile 32x16, 512 threads, template radius R, sliding-window pairs,
// monotone-map trick, streaming stores, min 4 blocks/SM.
// ---------------------------------------------------------------------------
#define TTX 32
#define TTY 16
#define RMAX 4
#define INW_MAX (TTX + 4 * RMAX)
#define INH_MAX (TTY + 4 * RMAX)
#define HMW_MAX (TTX + 2 * RMAX)
#define EH_MAX  (TTY + 2 * RMAX)
#define NT (TTX * TTY)

struct SmemT {
    float s_in[2][INH_MAX][INW_MAX];
    float s_hm[2][INH_MAX][HMW_MAX];
    float s_er[2][EH_MAX][HMW_MAX];
    float s_hx[2][EH_MAX][TTX];
};

template<int R>
__device__ __forceinline__ void open_body(SmemT& S, float* __restrict__ out)
{
    constexpr int INW = TTX + 4 * R;
    constexpr int INH = TTY + 4 * R;
    constexpr int HMW = TTX + 2 * R;
    constexpr int EH  = TTY + 2 * R;
    constexpr int WIN = 2 * R;

    const float PINF = __int_as_float(0x7f800000);
    const float NINF = __int_as_float(0xff800000);

    int b  = blockIdx.z;
    int ox = blockIdx.x * TTX;
    int oy = blockIdx.y * TTY;
    int tid = threadIdx.y * TTX + threadIdx.x;

    int txx = threadIdx.x, tyy = threadIdx.y;
    int gx = ox + txx, gy = oy + tyy;
    size_t p = (size_t)gy * WW + gx;
    float4 a0 = reinterpret_cast<const float4*>(g_acc)[(size_t)(0 * BB + b) * HW + p];
    float4 a1 = reinterpret_cast<const float4*>(g_acc)[(size_t)(1 * BB + b) * HW + p];
    float i0 = 1.0f / (a0.w + EPSF);
    float i1 = 1.0f / (a1.w + EPSF);
    float f01r = a0.x * i0, f01g = a0.y * i0, f01b = a0.z * i0;
    float f10r = a1.x * i1, f10g = a1.y * i1, f10b = a1.z * i1;

    // Stage 1: RAW w into halo; +inf outside (erosion pad)
    {
        const float* w0 = g_acc + ((size_t)(0 * BB + b) * HW << 2) + 3;
        const float* w1 = g_acc + ((size_t)(1 * BB + b) * HW << 2) + 3;
#pragma unroll 2
        for (int idx = tid; idx < INH * INW; idx += NT) {
            int iy = idx / INW;
            int ix = idx - iy * INW;
            int hy = oy - 2 * R + iy;
            int hx = ox - 2 * R + ix;
            float v0 = PINF, v1 = PINF;
            if ((unsigned)hy < (unsigned)HH && (unsigned)hx < (unsigned)WW) {
                size_t o = ((size_t)hy * WW + hx) << 2;
                v0 = w0[o];
                v1 = w1[o];
            }
            S.s_in[0][iy][ix] = v0;
            S.s_in[1][iy][ix] = v1;
        }
    }
    __syncthreads();

    // Stage 2: horizontal min, paired outputs
    {
        constexpr int HMW2 = HMW / 2;
        for (int idx = tid; idx < INH * HMW2; idx += NT) {
            int iy = idx / HMW2;
            int hx = (idx - iy * HMW2) * 2;
            float c0 = S.s_in[0][iy][hx + 1];
            float c1 = S.s_in[1][iy][hx + 1];
#pragma unroll
            for (int dd = 2; dd <= WIN; ++dd) {
                c0 = fminf(c0, S.s_in[0][iy][hx + dd]);
                c1 = fminf(c1, S.s_in[1][iy][hx + dd]);
            }
            S.s_hm[0][iy][hx]     = fminf(S.s_in[0][iy][hx], c0);
            S.s_hm[1][iy][hx]     = fminf(S.s_in[1][iy][hx], c1);
            S.s_hm[0][iy][hx + 1] = fminf(c0, S.s_in[0][iy][hx + WIN + 1]);
            S.s_hm[1][iy][hx + 1] = fminf(c1, S.s_in[1][iy][hx + WIN + 1]);
        }
    }
    __syncthreads();

    // Stage 3: vertical min -> erosion, paired; out-of-image -> -inf
    {
        constexpr int EH2 = EH / 2;
        for (int idx = tid; idx < EH2 * HMW; idx += NT) {
            int ep = idx / HMW;
            int hx = idx - ep * HMW;
            int ey = ep * 2;
            int hgx = ox - R + hx;
            bool colok = (unsigned)hgx < (unsigned)WW;
            int hy0 = oy - R + ey;
            float c0 = S.s_hm[0][ey + 1][hx];
            float c1 = S.s_hm[1][ey + 1][hx];
#pragma unroll
            for (int dd = 2; dd <= WIN; ++dd) {
                c0 = fminf(c0, S.s_hm[0][ey + dd][hx]);
                c1 = fminf(c1, S.s_hm[1][ey + dd][hx]);
            }
            bool ok0 = colok && ((unsigned)hy0 < (unsigned)HH);
            bool ok1 = colok && ((unsigned)(hy0 + 1) < (unsigned)HH);
            S.s_er[0][ey][hx]     = ok0 ? fminf(S.s_hm[0][ey][hx], c0) : NINF;
            S.s_er[1][ey][hx]     = ok0 ? fminf(S.s_hm[1][ey][hx], c1) : NINF;
            S.s_er[0][ey + 1][hx] = ok1 ? fminf(c0, S.s_hm[0][ey + WIN + 1][hx]) : NINF;
            S.s_er[1][ey + 1][hx] = ok1 ? fminf(c1, S.s_hm[1][ey + WIN + 1][hx]) : NINF;
        }
    }
    __syncthreads();

    // Stage 4: horizontal max, paired
    {
        constexpr int TTX2 = TTX / 2;
        for (int idx = tid; idx < EH * TTX2; idx += NT) {
            int ey = idx / TTX2;
            int xx = (idx - ey * TTX2) * 2;
            float c0 = S.s_er[0][ey][xx + 1];
            float c1 = S.s_er[1][ey][xx + 1];
#pragma unroll
            for (int dd = 2; dd <= WIN; ++dd) {
                c0 = fmaxf(c0, S.s_er[0][ey][xx + dd]);
                c1 = fmaxf(c1, S.s_er[1][ey][xx + dd]);
            }
            S.s_hx[0][ey][xx]     = fmaxf(S.s_er[0][ey][xx], c0);
            S.s_hx[1][ey][xx]     = fmaxf(S.s_er[1][ey][xx], c1);
            S.s_hx[0][ey][xx + 1] = fmaxf(c0, S.s_er[0][ey][xx + WIN + 1]);
            S.s_hx[1][ey][xx + 1] = fmaxf(c1, S.s_er[1][ey][xx + WIN + 1]);
        }
    }
    __syncthreads();

    // Stage 5: vertical max -> opened raw w; f(w)=w/(w+eps); compose.
    {
        float w01 = S.s_hx[0][tyy][txx];
        float w10 = S.s_hx[1][tyy][txx];
#pragma unroll
        for (int dd = 1; dd <= WIN; ++dd) {
            w01 = fmaxf(w01, S.s_hx[0][tyy + dd][txx]);
            w10 = fmaxf(w10, S.s_hx[1][tyy + dd][txx]);
        }
        float m01 = w01 / (w01 + EPSF);
        float m10 = w10 / (w10 + EPSF);

        float* ob = out + (size_t)b * 18 * HW;
        __stcs(&ob[(size_t)0  * HW + p], m01 * f01r + (1.0f - m01) * f10r);
        __stcs(&ob[(size_t)1  * HW + p], m01 * f01g + (1.0f - m01) * f10g);
        __stcs(&ob[(size_t)2  * HW + p], m01 * f01b + (1.0f - m01) * f10b);
        __stcs(&ob[(size_t)3  * HW + p], m10 * f10r + (1.0f - m10) * f01r);
        __stcs(&ob[(size_t)4  * HW + p], m10 * f10g + (1.0f - m10) * f01g);
        __stcs(&ob[(size_t)5  * HW + p], m10 * f10b + (1.0f - m10) * f01b);
        __stcs(&ob[(size_t)6  * HW + p], f01r);
        __stcs(&ob[(size_t)7  * HW + p], f01g);
        __stcs(&ob[(size_t)8  * HW + p], f01b);
        __stcs(&ob[(size_t)9  * HW + p], f10r);
        __stcs(&ob[(size_t)10 * HW + p], f10g);
        __stcs(&ob[(size_t)11 * HW + p], f10b);
        __stcs(&ob[(size_t)16 * HW + p], m01);
        __stcs(&ob[(size_t)17 * HW + p], m10);
    }
}

__global__ void __launch_bounds__(NT, 4) open_compose_kernel(
    const int* __restrict__ kptr, float* __restrict__ out)
{
    __shared__ SmemT S;

    int kk = kptr[0];
    int r = (kk >= 2) ? (kk - 1) / 2 : 0;
    if (r > RMAX) r = RMAX;

    switch (r) {
        case 0: open_body<0>(S, out); break;
        case 1: open_body<1>(S, out); break;
        case 2: open_body<2>(S, out); break;
        case 3: open_body<3>(S, out); break;
        default: open_body<4>(S, out); break;
    }
}

// ---------------------------------------------------------------------------
extern "C" void kernel_launch(void* const* d_in, const int* in_sizes, int n_in,
                              void* d_out, int out_size)
{
    const float* img0  = (const float*)d_in[0];
    const float* img1  = (const float*)d_in[1];
    const float* flow0 = (const float*)d_in[2];
    const float* flow1 = (const float*)d_in[3];
    const float* z0    = (const float*)d_in[4];
    const float* z1    = (const float*)d_in[5];
    const int*   kptr  = (const int*)d_in[6];
    float* out = (float*)d_out;

    // One-time host-side resources (no device memory involved)
    static cudaStream_t s1 = nullptr, sM = nullptr, sC = nullptr;
    static cudaEvent_t evFork = nullptr, evJoin1 = nullptr, evJoinC = nullptr;
    static cudaEvent_t evMs[4] = {nullptr, nullptr, nullptr, nullptr};
    if (s1 == nullptr) {
        cudaStreamCreateWithFlags(&s1, cudaStreamNonBlocking);
        cudaStreamCreateWithFlags(&sM, cudaStreamNonBlocking);
        cudaStreamCreateWithFlags(&sC, cudaStreamNonBlocking);
        cudaEventCreateWithFlags(&evFork, cudaEventDisableTiming);
        cudaEventCreateWithFlags(&evJoin1, cudaEventDisableTiming);
        cudaEventCreateWithFlags(&evJoinC, cudaEventDisableTiming);
        for (int i = 0; i < 4; ++i)
            cudaEventCreateWithFlags(&evMs[i], cudaEventDisableTiming);
    }

    void* accPtr = nullptr;
    cudaGetSymbolAddress(&accPtr, g_acc);
    float4* acc = reinterpret_cast<float4*>(accPtr);
    const size_t chunkF4 = (size_t)HW;               // one (dir,batch) chunk
    const size_t chunkBytes = chunkF4 * sizeof(float4);

    int threads = 256;
    int blocksHW = (HW + threads - 1) / threads;

    // Fork
    cudaEventRecord(evFork, 0);
    cudaStreamWaitEvent(s1, evFork, 0);
    cudaStreamWaitEvent(sM, evFork, 0);
    cudaStreamWaitEvent(sC, evFork, 0);

    // Memset stream: clear 4 chunks, signal each.
    // chunk layout: [d0b0][d0b1][d1b0][d1b1]
    for (int c = 0; c < 4; ++c) {
        cudaMemsetAsync(acc + (size_t)c * chunkF4, 0, chunkBytes, sM);
        cudaEventRecord(evMs[c], sM);
    }

    // Flow-copy stream: channels 12-15, concurrent with splats (DRAM-bound
    // work under the L2-atomic-bound splat phase).
    {
        int fblocks = (FQ + threads - 1) / threads;
        flow_copy_kernel<<<fblocks, threads, 0, sC>>>(
            reinterpret_cast<const float4*>(flow0),
            reinterpret_cast<const float4*>(flow1), 
            reinterpret_cast<float4*>(out));
        cudaEventRecord(evJoinC, sC);
    }

    // Main stream: dir0 (img0, flow1, z1) both batches
    cudaStreamWaitEvent(0, evMs[0], 0);
    splat_db_kernel<<<blocksHW, threads, 0, 0>>>(
        img0, flow1, z1, acc + 0 * chunkF4);
    cudaStreamWaitEvent(0, evMs[1], 0);
    splat_db_kernel<<<blocksHW, threads, 0, 0>>>(
        img0 + (size_t)3 * HW, flow1 + (size_t)2 * HW, z1 + (size_t)HW,
        acc + 1 * chunkF4);

    // s1: dir1 (img1, flow0, z0) both batches
    cudaStreamWaitEvent(s1, evMs[2], 0);
    splat_db_kernel<<<blocksHW, threads, 0, s1>>>(
        img1, flow0, z0, acc + 2 * chunkF4);
    cudaStreamWaitEvent(s1, evMs[3], 0);
    splat_db_kernel<<<blocksHW, threads, 0, s1>>>(
        img1 + (size_t)3 * HW, flow0 + (size_t)2 * HW, z0 + (size_t)HW,
        acc + 3 * chunkF4);
    cudaEventRecord(evJoin1, s1);

    // Join splats, run open/compose
    cudaStreamWaitEvent(0, evJoin1, 0);
    dim3 gblk(TTX, TTY, 1);
    dim3 ggrid(WW / TTX, HH / TTY, BB);
    open_compose_kernel<<<ggrid, gblk, 0, 0>>>(kptr, out);

    // Join flow-copy stream before capture end (disjoint outputs; no hazard)
    cudaStreamWaitEvent(0, evJoinC, 0);
}

// round 10
// speedup vs baseline: 1.0909x; 1.0909x over previous
#include <cuda_runtime.h>
#include <math.h>

#define BB 2
#define HH 720
#define WW 1280
#define HW (HH*WW)
#define NPIX (BB*HW)
#define EPSF 1e-7f

// Scratch: splat accumulators [dir][b][pixel][4ch]  (~59 MB)
__device__ __align__(16) float g_acc[(size_t)2 * BB * HW * 4];

// ---------------------------------------------------------------------------
// Splat kernel, ONE direction per launch (1 px/thread — measured REDG floor).
// sm_90+ float4 atomicAdd -> one RED.E.128 per corner.
// ---------------------------------------------------------------------------
__global__ void __launch_bounds__(256) splat_dir_kernel(
    const float* __restrict__ img, const float* __restrict__ fl,
    const float* __restrict__ zz, float4* __restrict__ accBase)
{
    int i = blockIdx.x * blockDim.x + threadIdx.x;
    if (i >= NPIX) return;
    int b = i / HW;
    int p = i - b * HW;
    int y = p / WW;
    int x = p - y * WW;

    float fx = (float)x + 0.5f * fl[(size_t)(b * 2 + 1) * HW + p];
    float fy = (float)y + 0.5f * fl[(size_t)(b * 2 + 0) * HW + p];
    float w  = __expf(zz[(size_t)b * HW + p]);
    float vr = img[(size_t)(b * 3 + 0) * HW + p] * w;
    float vg = img[(size_t)(b * 3 + 1) * HW + p] * w;
    float vb = img[(size_t)(b * 3 + 2) * HW + p] * w;

    float x0f = floorf(fx), y0f = floorf(fy);
    int ix0 = (int)x0f, iy0 = (int)y0f;
    float ax = fx - x0f, ay = fy - y0f;

    float4* acc = accBase + (size_t)b * HW;
#pragma unroll
    for (int cy = 0; cy < 2; ++cy) {
        int ty = iy0 + cy;
        if ((unsigned)ty >= (unsigned)HH) continue;
        float wy = cy ? ay : (1.0f - ay);
#pragma unroll
        for (int cx = 0; cx < 2; ++cx) {
            int tx = ix0 + cx;
            if ((unsigned)tx >= (unsigned)WW) continue;
            float wt = wy * (cx ? ax : (1.0f - ax));
            atomicAdd(acc + ((size_t)ty * WW + tx),
                      make_float4(vr * wt, vg * wt, vb * wt, w * wt));
        }
    }
}

// ---------------------------------------------------------------------------
// Flow channels (12-15): out = 0.5 * flow. DRAM-bound; scheduled under the
// L2-atomic-bound splat window (after memsets finish).
// ---------------------------------------------------------------------------
#define FQ (BB * 2 * HW / 4)
__global__ void __launch_bounds__(256) flow_copy_kernel(
    const float4* __restrict__ f0, const float4* __restrict__ f1,
    float4* __restrict__ out)
{
    int i = blockIdx.x * blockDim.x + threadIdx.x;
    if (i >= FQ) return;
    const int CH4 = HW / 4;
    int b = i / (2 * CH4);
    int rem = i - b * (2 * CH4);
    int c = rem / CH4;
    int p4 = rem - c * CH4;

    float4 q0 = __ldcs(f0 + i);
    float4 q1 = __ldcs(f1 + i);
    float4 h0 = make_float4(0.5f*q0.x, 0.5f*q0.y, 0.5f*q0.z, 0.5f*q0.w);
    float4 h1 = make_float4(0.5f*q1.x, 0.5f*q1.y, 0.5f*q1.z, 0.5f*q1.w);
    __stcs(out + (size_t)(b * 18 + 12 + c) * CH4 + p4, h0);
    __stcs(out + (size_t)(b * 18 + 14 + c) * CH4 + p4, h1);
}

// ---------------------------------------------------------------------------
// Fused normalize + morphological open + compose (flows excluded).
// Tile 32x16, 512 threads, template radius R, sliding-window pairs,
// monotone-map trick, streaming stores, min 4 blocks/SM.
// ---------------------------------------------------------------------------
#define TTX 32
#define TTY 16
#define RMAX 4
#define INW_MAX (TTX + 4 * RMAX)
#define INH_MAX (TTY + 4 * RMAX)
#define HMW_MAX (TTX + 2 * RMAX)
#define EH_MAX  (TTY + 2 * RMAX)
#define NT (TTX * TTY)

struct SmemT {
    float s_in[2][INH_MAX][INW_MAX];
    float s_hm[2][INH_MAX][HMW_MAX];
    float s_er[2][EH_MAX][HMW_MAX];
    float s_hx[2][EH_MAX][TTX];
};

template<int R>
__device__ __forceinline__ void open_body(SmemT& S, float* __restrict__ out)
{
    constexpr int INW = TTX + 4 * R;
    constexpr int INH = TTY + 4 * R;
    constexpr int HMW = TTX + 2 * R;
    constexpr int EH  = TTY + 2 * R;
    constexpr int WIN = 2 * R;

    const float PINF = __int_as_float(0x7f800000);
    const float NINF = __int_as_float(0xff800000);

    int b  = blockIdx.z;
    int ox = blockIdx.x * TTX;
    int oy = blockIdx.y * TTY;
    int tid = threadIdx.y * TTX + threadIdx.x;

    int txx = threadIdx.x, tyy = threadIdx.y;
    int gx = ox + txx, gy = oy + tyy;
    size_t p = (size_t)gy * WW + gx;
    float4 a0 = reinterpret_cast<const float4*>(g_acc)[(size_t)(0 * BB + b) * HW + p];
    float4 a1 = reinterpret_cast<const float4*>(g_acc)[(size_t)(1 * BB + b) * HW + p];
    float i0 = 1.0f / (a0.w + EPSF);
    float i1 = 1.0f / (a1.w + EPSF);
    float f01r = a0.x * i0, f01g = a0.y * i0, f01b = a0.z * i0;
    float f10r = a1.x * i1, f10g = a1.y * i1, f10b = a1.z * i1;

    // Stage 1: RAW w into halo; +inf outside (erosion pad)
    {
        const float* w0 = g_acc + ((size_t)(0 * BB + b) * HW << 2) + 3;
        const float* w1 = g_acc + ((size_t)(1 * BB + b) * HW << 2) + 3;
#pragma unroll 2
        for (int idx = tid; idx < INH * INW; idx += NT) {
            int iy = idx / INW;
            int ix = idx - iy * INW;
            int hy = oy - 2 * R + iy;
            int hx = ox - 2 * R + ix;
            float v0 = PINF, v1 = PINF;
            if ((unsigned)hy < (unsigned)HH && (unsigned)hx < (unsigned)WW) {
                size_t o = ((size_t)hy * WW + hx) << 2;
                v0 = w0[o];
                v1 = w1[o];
            }
            S.s_in[0][iy][ix] = v0;
            S.s_in[1][iy][ix] = v1;
        }
    }
    __syncthreads();

    // Stage 2: horizontal min, paired outputs
    {
        constexpr int HMW2 = HMW / 2;
        for (int idx = tid; idx < INH * HMW2; idx += NT) {
            int iy = idx / HMW2;
            int hx = (idx - iy * HMW2) * 2;
            float c0 = S.s_in[0][iy][hx + 1];
            float c1 = S.s_in[1][iy][hx + 1];
#pragma unroll
            for (int dd = 2; dd <= WIN; ++dd) {
                c0 = fminf(c0, S.s_in[0][iy][hx + dd]);
                c1 = fminf(c1, S.s_in[1][iy][hx + dd]);
            }
            S.s_hm[0][iy][hx]     = fminf(S.s_in[0][iy][hx], c0);
            S.s_hm[1][iy][hx]     = fminf(S.s_in[1][iy][hx], c1);
            S.s_hm[0][iy][hx + 1] = fminf(c0, S.s_in[0][iy][hx + WIN + 1]);
            S.s_hm[1][iy][hx + 1] = fminf(c1, S.s_in[1][iy][hx + WIN + 1]);
        }
    }
    __syncthreads();

    // Stage 3: vertical min -> erosion, paired; out-of-image -> -inf
    {
        constexpr int EH2 = EH / 2;
        for (int idx = tid; idx < EH2 * HMW; idx += NT) {
            int ep = idx / HMW;
            int hx = idx - ep * HMW;
            int ey = ep * 2;
            int hgx = ox - R + hx;
            bool colok = (unsigned)hgx < (unsigned)WW;
            int hy0 = oy - R + ey;
            float c0 = S.s_hm[0][ey + 1][hx];
            float c1 = S.s_hm[1][ey + 1][hx];
#pragma unroll
            for (int dd = 2; dd <= WIN; ++dd) {
                c0 = fminf(c0, S.s_hm[0][ey + dd][hx]);
                c1 = fminf(c1, S.s_hm[1][ey + dd][hx]);
            }
            bool ok0 = colok && ((unsigned)hy0 < (unsigned)HH);
            bool ok1 = colok && ((unsigned)(hy0 + 1) < (unsigned)HH);
            S.s_er[0][ey][hx]     = ok0 ? fminf(S.s_hm[0][ey][hx], c0) : NINF;
            S.s_er[1][ey][hx]     = ok0 ? fminf(S.s_hm[1][ey][hx], c1) : NINF;
            S.s_er[0][ey + 1][hx] = ok1 ? fminf(c0, S.s_hm[0][ey + WIN + 1][hx]) : NINF;
            S.s_er[1][ey + 1][hx] = ok1 ? fminf(c1, S.s_hm[1][ey + WIN + 1][hx]) : NINF;
        }
    }
    __syncthreads();

    // Stage 4: horizontal max, paired
    {
        constexpr int TTX2 = TTX / 2;
        for (int idx = tid; idx < EH * TTX2; idx += NT) {
            int ey = idx / TTX2;
            int xx = (idx - ey * TTX2) * 2;
            float c0 = S.s_er[0][ey][xx + 1];
            float c1 = S.s_er[1][ey][xx + 1];
#pragma unroll
            for (int dd = 2; dd <= WIN; ++dd) {
                c0 = fmaxf(c0, S.s_er[0][ey][xx + dd]);
                c1 = fmaxf(c1, S.s_er[1][ey][xx + dd]);
            }
            S.s_hx[0][ey][xx]     = fmaxf(S.s_er[0][ey][xx], c0);
            S.s_hx[1][ey][xx]     = fmaxf(S.s_er[1][ey][xx], c1);
            S.s_hx[0][ey][xx + 1] = fmaxf(c0, S.s_er[0][ey][xx + WIN + 1]);
            S.s_hx[1][ey][xx + 1] = fmaxf(c1, S.s_er[1][ey][xx + WIN + 1]);
        }
    }
    __syncthreads();

    // Stage 5: vertical max -> opened raw w; f(w)=w/(w+eps); compose.
    {
        float w01 = S.s_hx[0][tyy][txx];
        float w10 = S.s_hx[1][tyy][txx];
#pragma unroll
        for (int dd = 1; dd <= WIN; ++dd) {
            w01 = fmaxf(w01, S.s_hx[0][tyy + dd][txx]);
            w10 = fmaxf(w10, S.s_hx[1][tyy + dd][txx]);
        }
        float m01 = w01 / (w01 + EPSF);
        float m10 = w10 / (w10 + EPSF);

        float* ob = out + (size_t)b * 18 * HW;
        __stcs(&ob[(size_t)0  * HW + p], m01 * f01r + (1.0f - m01) * f10r);
        __stcs(&ob[(size_t)1  * HW + p], m01 * f01g + (1.0f - m01) * f10g);
        __stcs(&ob[(size_t)2  * HW + p], m01 * f01b + (1.0f - m01) * f10b);
        __stcs(&ob[(size_t)3  * HW + p], m10 * f10r + (1.0f - m10) * f01r);
        __stcs(&ob[(size_t)4  * HW + p], m10 * f10g + (1.0f - m10) * f01g);
        __stcs(&ob[(size_t)5  * HW + p], m10 * f10b + (1.0f - m10) * f01b);
        __stcs(&ob[(size_t)6  * HW + p], f01r);
        __stcs(&ob[(size_t)7  * HW + p], f01g);
        __stcs(&ob[(size_t)8  * HW + p], f01b);
        __stcs(&ob[(size_t)9  * HW + p], f10r);
        __stcs(&ob[(size_t)10 * HW + p], f10g);
        __stcs(&ob[(size_t)11 * HW + p], f10b);
        __stcs(&ob[(size_t)16 * HW + p], m01);
        __stcs(&ob[(size_t)17 * HW + p], m10);
    }
}

__global__ void __launch_bounds__(NT, 4) open_compose_kernel(
    const int* __restrict__ kptr, float* __restrict__ out)
{
    __shared__ SmemT S;

    int kk = kptr[0];
    int r = (kk >= 2) ? (kk - 1) / 2 : 0;
    if (r > RMAX) r = RMAX;

    switch (r) {
        case 0: open_body<0>(S, out); break;
        case 1: open_body<1>(S, out); break;
        case 2: open_body<2>(S, out); break;
        case 3: open_body<3>(S, out); break;
        default: open_body<4>(S, out); break;
    }
}

// ---------------------------------------------------------------------------
extern "C" void kernel_launch(void* const* d_in, const int* in_sizes, int n_in,
                              void* d_out, int out_size)
{
    const float* img0  = (const float*)d_in[0];
    const float* img1  = (const float*)d_in[1];
    const float* flow0 = (const float*)d_in[2];
    const float* flow1 = (const float*)d_in[3];
    const float* z0    = (const float*)d_in[4];
    const float* z1    = (const float*)d_in[5];
    const int*   kptr  = (const int*)d_in[6];
    float* out = (float*)d_out;

    // One-time host-side resources (no device memory involved)
    static cudaStream_t s1 = nullptr, sC = nullptr;
    static cudaEvent_t evFork = nullptr, evJoin1 = nullptr, evJoinC = nullptr;
    static cudaEvent_t evM0 = nullptr, evM1 = nullptr;
    if (s1 == nullptr) {
        cudaStreamCreateWithFlags(&s1, cudaStreamNonBlocking);
        cudaStreamCreateWithFlags(&sC, cudaStreamNonBlocking);
        cudaEventCreateWithFlags(&evFork, cudaEventDisableTiming);
        cudaEventCreateWithFlags(&evJoin1, cudaEventDisableTiming);
        cudaEventCreateWithFlags(&evJoinC, cudaEventDisableTiming);
        cudaEventCreateWithFlags(&evM0, cudaEventDisableTiming);
        cudaEventCreateWithFlags(&evM1, cudaEventDisableTiming);
    }

    void* accPtr = nullptr;
    cudaGetSymbolAddress(&accPtr, g_acc);
    const size_t dirBytes = sizeof(float) * (size_t)BB * HW * 4;
    float4* acc_d0 = reinterpret_cast<float4*>(accPtr);
    float4* acc_d1 = acc_d0 + (size_t)BB * HW;

    int threads = 256;
    int blocks = (NPIX + threads - 1) / threads;

    // Fork
    cudaEventRecord(evFork, 0);
    cudaStreamWaitEvent(s1, evFork, 0);
    cudaStreamWaitEvent(sC, evFork, 0);

    // Main stream: dir 0 memset + splat (img0, flow1, z1)
    cudaMemsetAsync(acc_d0, 0, dirBytes, 0);
    cudaEventRecord(evM0, 0);
    splat_dir_kernel<<<blocks, threads, 0, 0>>>(img0, flow1, z1, acc_d0);

    // Side stream s1: dir 1 memset + splat (img1, flow0, z0)
    cudaMemsetAsync(acc_d1, 0, dirBytes, s1);
    cudaEventRecord(evM1, s1);
    splat_dir_kernel<<<blocks, threads, 0, s1>>>(img1, flow0, z0, acc_d1);
    cudaEventRecord(evJoin1, s1);

    // Flow-copy stream: waits for BOTH memsets (keeps DRAM lead-in clean),
    // then runs under the atomic-bound splat window.
    cudaStreamWaitEvent(sC, evM0, 0);
    cudaStreamWaitEvent(sC, evM1, 0);
    {
        int fblocks = (FQ + threads - 1) / threads;
        flow_copy_kernel<<<fblocks, threads, 0, sC>>>(
            reinterpret_cast<const float4*>(flow0),
            reinterpret_cast<const float4*>(flow1),
            reinterpret_cast<float4*>(out));
        cudaEventRecord(evJoinC, sC);
    }

    // Join splats, run open/compose
    cudaStreamWaitEvent(0, evJoin1, 0);
    dim3 gblk(TTX, TTY, 1);
    dim3 ggrid(WW / TTX, HH / TTY, BB);
    open_compose_kernel<<<ggrid, gblk, 0, 0>>>(kptr, out);

    // Join flow-copy stream before capture end (disjoint outputs; no hazard)
    cudaStreamWaitEvent(0, evJoinC, 0);
}